// round 16
// baseline (speedup 1.0000x reference)
#include <cuda_runtime.h>
#include <cuda_fp16.h>
#include <cstdint>

#define Bn 4
#define Cn 16
#define Hn 512
#define Wn 512
#define HWn (Hn*Wn)        // 262144
#define NPIX (Bn*HWn)      // 1048576
#define NOUT (Bn*Cn*HWn)   // 16777216
#define EPSF 1e-10f

// Channel-contiguous f16 accumulator A': [pixel][16 x half] = 32B/record. 32 MB.
__device__ __half2 g_Ah[NOUT / 2];
// Weight-sum accumulator D, f32, 2x2-BLOCKED layout per batch:
//   cell (i,j) -> ((i>>1)*256 + (j>>1))*4 + (i&1)*2 + (j&1). 4 MB.
__device__ float g_D[NPIX];

// PDL primitives
__device__ __forceinline__ void pdl_trigger() {
    asm volatile("griddepcontrol.launch_dependents;");
}
__device__ __forceinline__ void pdl_wait() {
    asm volatile("griddepcontrol.wait;" ::: "memory");
}

// ---------------------------------------------------------------------------
// Kernel 1: zero scratch A' and D, then release dependents (PDL).
// ---------------------------------------------------------------------------
__global__ void zero_kernel() {
    const int n_a4 = (NOUT * 2) / 16;   // 2097152 float4-units of A (32MB)
    const int n_d4 = NPIX / 4;          // 262144
    int idx = blockIdx.x * blockDim.x + threadIdx.x;
    float4 z = make_float4(0.f, 0.f, 0.f, 0.f);
    if (idx < n_a4) {
        reinterpret_cast<float4*>(g_Ah)[idx] = z;
    } else if (idx < n_a4 + n_d4) {
        reinterpret_cast<float4*>(g_D)[idx - n_a4] = z;
    }
    pdl_trigger();
}

// ---------------------------------------------------------------------------
// f16 corner emission: 8 HMUL2 -> 2 x 16B v4.f16x2 RED messages (ISA max).
// ---------------------------------------------------------------------------
__device__ __forceinline__ void emit_corner_h(bool v, __half2* base, float w,
                                              const uint32_t* xh) {
    if (!v) return;
    __half2 wh = __float2half2_rn(w);
    uint32_t m[8];
#pragma unroll
    for (int k = 0; k < 8; k++) {
        __half2 prod = __hmul2(*reinterpret_cast<const __half2*>(&xh[k]), wh);
        m[k] = *reinterpret_cast<uint32_t*>(&prod);
    }
    asm volatile("red.global.add.noftz.v4.f16x2 [%0], {%1,%2,%3,%4};"
                 :: "l"(base), "r"(m[0]), "r"(m[1]), "r"(m[2]), "r"(m[3]) : "memory");
    asm volatile("red.global.add.noftz.v4.f16x2 [%0], {%1,%2,%3,%4};"
                 :: "l"(base + 4), "r"(m[4]), "r"(m[5]), "r"(m[6]), "r"(m[7]) : "memory");
}

__device__ __forceinline__ void red4(float* addr, float a, float b, float c, float d) {
    asm volatile("red.global.add.v4.f32 [%0], {%1,%2,%3,%4};"
                 :: "l"(addr), "f"(a), "f"(b), "f"(c), "f"(d) : "memory");
}

// ---------------------------------------------------------------------------
// Kernel 2: scatter. One thread per source pixel.
// PDL: prologue (grid + x loads + weights + f16 convert) overlaps zero's
// drain; griddepcontrol.wait guards the REDs.
// ---------------------------------------------------------------------------
__global__ void scatter_kernel(const float* __restrict__ x,
                               const float* __restrict__ grid) {
    int p = blockIdx.x * blockDim.x + threadIdx.x;
    if (p >= NPIX) { pdl_wait(); pdl_trigger(); return; }

    float2 gv = __ldcs(reinterpret_cast<const float2*>(grid) + p);

    int b   = p >> 18;
    int pix = p & (HWn - 1);

    // Prologue: 16 x-loads issued before the PDL wait (overlap zero's tail).
    const float* xp = x + (size_t)b * Cn * HWn + pix;
    float xv[16];
#pragma unroll
    for (int c = 0; c < Cn; c++) xv[c] = __ldcs(xp + c * HWn);

    float g0 = (gv.x + 1.0f) * 0.5f;
    float g1 = (gv.y + 1.0f) * 0.5f;
    float gi = fminf(fmaxf(fmaf(g0, 512.0f, 1.0f), 0.0f), 513.0f);
    float gj = fminf(fmaxf(fmaf(g1, 512.0f, 1.0f), 0.0f), 513.0f);

    int ii0 = (int)gi;
    int jj0 = (int)gj;
    float fi = gi - (float)ii0;
    float fj = gj - (float)jj0;
    float wi0 = 1.0f - fi, wi1 = fi;
    float wj0 = 1.0f - fj, wj1 = fj;

    int oi0 = ii0 - 1, oi1 = ii0;
    int oj0 = jj0 - 1, oj1 = jj0;
    bool vi0 = (unsigned)oi0 < (unsigned)Hn;
    bool vi1 = (unsigned)oi1 < (unsigned)Hn;
    bool vj0 = (unsigned)oj0 < (unsigned)Wn;
    bool vj1 = (unsigned)oj1 < (unsigned)Wn;

    bool  v00 = vi0 && vj0,       v01 = vi0 && vj1;
    bool  v10 = vi1 && vj0,       v11 = vi1 && vj1;
    int   o00 = oi0 * Wn + oj0,   o01 = oi0 * Wn + oj1;
    int   o10 = oi1 * Wn + oj0,   o11 = oi1 * Wn + oj1;
    float w00 = wi0 * wj0,        w01 = wi0 * wj1;
    float w10 = wi1 * wj0,        w11 = wi1 * wj1;

    // Convert x to f16x2 once (still pre-wait: pure register work).
    uint32_t xh[8];
#pragma unroll
    for (int k = 0; k < 8; k++) {
        __half2 h = __floats2half2_rn(xv[2 * k], xv[2 * k + 1]);
        xh[k] = *reinterpret_cast<uint32_t*>(&h);
    }

    // Wait for zero_kernel's stores to be visible, then emit all REDs.
    pdl_wait();

    // ---- D accumulation into 2x2-blocked layout ----
    float* Db = g_D + b * HWn;
    int pi = oi0 & 1, pj = oj0 & 1;
    int ib0 = oi0 >> 1,       jb0 = oj0 >> 1;
    int ib1 = (oi0 + 1) >> 1, jb1 = (oj0 + 1) >> 1;
    if (pi == 0) {
        if (pj == 0) {
            if (vi0 && vj0)
                red4(Db + (ib0 * 256 + jb0) * 4, w00, w01, w10, w11);
        } else {
            if (vi0 && vj0) red4(Db + (ib0 * 256 + jb0) * 4, 0.f, w00, 0.f, w10);
            if (vi0 && vj1) red4(Db + (ib0 * 256 + jb1) * 4, w01, 0.f, w11, 0.f);
        }
    } else {
        if (pj == 0) {
            if (vj0 && vi0) red4(Db + (ib0 * 256 + jb0) * 4, 0.f, 0.f, w00, w01);
            if (vj0 && vi1) red4(Db + (ib1 * 256 + jb0) * 4, w10, w11, 0.f, 0.f);
        } else {
            if (v00) atomicAdd(Db + (ib0 * 256 + jb0) * 4 + 3, w00);
            if (v01) atomicAdd(Db + (ib0 * 256 + jb1) * 4 + 2, w01);
            if (v10) atomicAdd(Db + (ib1 * 256 + jb0) * 4 + 1, w10);
            if (v11) atomicAdd(Db + (ib1 * 256 + jb1) * 4 + 0, w11);
        }
    }

    __half2* Ab = g_Ah + (size_t)b * HWn * 8;   // 8 half2 per pixel record
    emit_corner_h(v00, Ab + (size_t)o00 * 8, w00, xh);
    emit_corner_h(v01, Ab + (size_t)o01 * 8, w01, xh);
    emit_corner_h(v10, Ab + (size_t)o10 * 8, w10, xh);
    emit_corner_h(v11, Ab + (size_t)o11 * 8, w11, xh);

    pdl_trigger();   // release normalize
}

// ---------------------------------------------------------------------------
// Kernel 3: normalize + transpose [pix][c](f16) -> [c][pix](f32).
// PDL secondary: index math pre-wait; A/D loads post-wait.
// ---------------------------------------------------------------------------
__device__ __forceinline__ float frcp(float a) {
    float r;
    asm("rcp.approx.ftz.f32 %0, %1;" : "=f"(r) : "f"(a));
    return r;
}

__global__ void normalize_kernel(float4* __restrict__ out4) {
    int t = blockIdx.x * blockDim.x + threadIdx.x;
    if (t >= NPIX) { pdl_wait(); return; }
    int q = t >> 2;      // pixel quad id
    int g = t & 3;       // channel group (channels 4g..4g+3)
    int lane = threadIdx.x & 31;
    int lane0 = lane & ~3;

    int p0  = q * 4;
    int b   = p0 >> 18;
    int pix = p0 & (HWn - 1);

    pdl_wait();          // scatter's REDs now visible

    float4 d;
    if (g == 0) {
        int i  = pix >> 9;          // row
        int jb = (pix & 511) >> 1;  // block-col of first pixel (even)
        const float4* D4 = reinterpret_cast<const float4*>(g_D);
        size_t blkbase = (size_t)b * (HWn / 4) + (i >> 1) * 256 + jb;
        float4 b0 = D4[blkbase];
        float4 b1 = D4[blkbase + 1];
        d = (i & 1) ? make_float4(b0.z, b0.w, b1.z, b1.w)
                    : make_float4(b0.x, b0.y, b1.x, b1.y);
    }
    d.x = __shfl_sync(0xFFFFFFFFu, d.x, lane0);
    d.y = __shfl_sync(0xFFFFFFFFu, d.y, lane0);
    d.z = __shfl_sync(0xFFFFFFFFu, d.z, lane0);
    d.w = __shfl_sync(0xFFFFFFFFu, d.w, lane0);

    float4 r, hf;
    bool bx = d.x > EPSF, by = d.y > EPSF, bz = d.z > EPSF, bw = d.w > EPSF;
    r.x = bx ? frcp(d.x + EPSF) : 0.0f;  hf.x = bx ? 0.0f : 1.0f;
    r.y = by ? frcp(d.y + EPSF) : 0.0f;  hf.y = by ? 0.0f : 1.0f;
    r.z = bz ? frcp(d.z + EPSF) : 0.0f;  hf.z = bz ? 0.0f : 1.0f;
    r.w = bw ? frcp(d.w + EPSF) : 0.0f;  hf.w = bw ? 0.0f : 1.0f;

    const uint2* A2 = reinterpret_cast<const uint2*>(g_Ah);
    uint2 u0 = A2[(size_t)(p0 + 0) * 4 + g];
    uint2 u1 = A2[(size_t)(p0 + 1) * 4 + g];
    uint2 u2 = A2[(size_t)(p0 + 2) * 4 + g];
    uint2 u3 = A2[(size_t)(p0 + 3) * 4 + g];

    float2 lo0 = __half22float2(*reinterpret_cast<const __half2*>(&u0.x));
    float2 hi0 = __half22float2(*reinterpret_cast<const __half2*>(&u0.y));
    float2 lo1 = __half22float2(*reinterpret_cast<const __half2*>(&u1.x));
    float2 hi1 = __half22float2(*reinterpret_cast<const __half2*>(&u1.y));
    float2 lo2 = __half22float2(*reinterpret_cast<const __half2*>(&u2.x));
    float2 hi2 = __half22float2(*reinterpret_cast<const __half2*>(&u2.y));
    float2 lo3 = __half22float2(*reinterpret_cast<const __half2*>(&u3.x));
    float2 hi3 = __half22float2(*reinterpret_cast<const __half2*>(&u3.y));

    float4 v0 = make_float4(fmaf(lo0.x, r.x, hf.x), fmaf(lo1.x, r.y, hf.y),
                            fmaf(lo2.x, r.z, hf.z), fmaf(lo3.x, r.w, hf.w));
    float4 v1 = make_float4(fmaf(lo0.y, r.x, hf.x), fmaf(lo1.y, r.y, hf.y),
                            fmaf(lo2.y, r.z, hf.z), fmaf(lo3.y, r.w, hf.w));
    float4 v2 = make_float4(fmaf(hi0.x, r.x, hf.x), fmaf(hi1.x, r.y, hf.y),
                            fmaf(hi2.x, r.z, hf.z), fmaf(hi3.x, r.w, hf.w));
    float4 v3 = make_float4(fmaf(hi0.y, r.x, hf.x), fmaf(hi1.y, r.y, hf.y),
                            fmaf(hi2.y, r.z, hf.z), fmaf(hi3.y, r.w, hf.w));

    float4* ob = out4 + ((size_t)b * Cn * HWn + pix) / 4;
    ob[(size_t)(4 * g + 0) * (HWn / 4)] = v0;
    ob[(size_t)(4 * g + 1) * (HWn / 4)] = v1;
    ob[(size_t)(4 * g + 2) * (HWn / 4)] = v2;
    ob[(size_t)(4 * g + 3) * (HWn / 4)] = v3;
}

// ---------------------------------------------------------------------------
extern "C" void kernel_launch(void* const* d_in, const int* in_sizes, int n_in,
                              void* d_out, int out_size) {
    const float* x    = (const float*)d_in[0];
    const float* grid = (const float*)d_in[1];
    float*       out  = (float*)d_out;

    {
        int total = (NOUT * 2) / 16 + NPIX / 4;
        zero_kernel<<<(total + 255) / 256, 256>>>();
    }

    cudaLaunchAttribute attrs[1];
    attrs[0].id = cudaLaunchAttributeProgrammaticStreamSerialization;
    attrs[0].val.programmaticStreamSerializationAllowed = 1;

    {
        cudaLaunchConfig_t cfg = {};
        cfg.gridDim  = dim3(NPIX / 256);
        cfg.blockDim = dim3(256);
        cfg.attrs    = attrs;
        cfg.numAttrs = 1;
        cudaLaunchKernelEx(&cfg, scatter_kernel, x, grid);
    }
    {
        cudaLaunchConfig_t cfg = {};
        cfg.gridDim  = dim3(NPIX / 256);
        cfg.blockDim = dim3(256);
        cfg.attrs    = attrs;
        cfg.numAttrs = 1;
        cudaLaunchKernelEx(&cfg, normalize_kernel, (float4*)out);
    }
}

// round 17
// speedup vs baseline: 1.0512x; 1.0512x over previous
#include <cuda_runtime.h>
#include <cuda_fp16.h>
#include <cstdint>

#define Bn 4
#define Cn 16
#define Hn 512
#define Wn 512
#define HWn (Hn*Wn)        // 262144
#define NPIX (Bn*HWn)      // 1048576
#define NOUT (Bn*Cn*HWn)   // 16777216
#define EPSF 1e-10f

// Channel-contiguous f16 accumulator A': [pixel][16 x half] = 32B/record. 32 MB.
__device__ __half2 g_Ah[NOUT / 2];
// Weight-sum accumulator D, f32, 2x2-BLOCKED layout per batch:
//   cell (i,j) -> ((i>>1)*256 + (j>>1))*4 + (i&1)*2 + (j&1)
// so a pixel's 2x2 corner patch hits ONE 16B quad when anchors are even. 4 MB.
__device__ float g_D[NPIX];

// ---------------------------------------------------------------------------
// Kernel 1: zero scratch A' and D (layout-agnostic).
// ---------------------------------------------------------------------------
__global__ void zero_kernel() {
    const int n_a4 = (NOUT * 2) / 16;   // 2097152 float4-units of A (32MB)
    const int n_d4 = NPIX / 4;          // 262144
    int idx = blockIdx.x * blockDim.x + threadIdx.x;
    float4 z = make_float4(0.f, 0.f, 0.f, 0.f);
    if (idx < n_a4) {
        reinterpret_cast<float4*>(g_Ah)[idx] = z;
    } else if (idx < n_a4 + n_d4) {
        reinterpret_cast<float4*>(g_D)[idx - n_a4] = z;
    }
}

// ---------------------------------------------------------------------------
// f16 corner emission: 8 HMUL2 -> 2 x 16B v4.f16x2 RED messages (ISA max).
// ---------------------------------------------------------------------------
__device__ __forceinline__ void emit_corner_h(bool v, __half2* base, float w,
                                              const uint32_t* xh) {
    if (!v) return;
    __half2 wh = __float2half2_rn(w);
    uint32_t m[8];
#pragma unroll
    for (int k = 0; k < 8; k++) {
        __half2 prod = __hmul2(*reinterpret_cast<const __half2*>(&xh[k]), wh);
        m[k] = *reinterpret_cast<uint32_t*>(&prod);
    }
    asm volatile("red.global.add.noftz.v4.f16x2 [%0], {%1,%2,%3,%4};"
                 :: "l"(base), "r"(m[0]), "r"(m[1]), "r"(m[2]), "r"(m[3]) : "memory");
    asm volatile("red.global.add.noftz.v4.f16x2 [%0], {%1,%2,%3,%4};"
                 :: "l"(base + 4), "r"(m[4]), "r"(m[5]), "r"(m[6]), "r"(m[7]) : "memory");
}

__device__ __forceinline__ void red4(float* addr, float a, float b, float c, float d) {
    asm volatile("red.global.add.v4.f32 [%0], {%1,%2,%3,%4};"
                 :: "l"(addr), "f"(a), "f"(b), "f"(c), "f"(d) : "memory");
}

// ---------------------------------------------------------------------------
// Kernel 2: scatter. One thread per source pixel.
// 8 x 16B A-messages + ~2.25 blocked-D messages = ~10.25 msgs/pixel.
// ---------------------------------------------------------------------------
__global__ void scatter_kernel(const float* __restrict__ x,
                               const float* __restrict__ grid) {
    int p = blockIdx.x * blockDim.x + threadIdx.x;
    if (p >= NPIX) return;

    float2 gv = __ldcs(reinterpret_cast<const float2*>(grid) + p);

    int b   = p >> 18;
    int pix = p & (HWn - 1);

    // Issue the 16 x-loads FIRST so their latency overlaps the D messages
    // (the asm "memory" clobbers below would otherwise pin them afterwards).
    const float* xp = x + (size_t)b * Cn * HWn + pix;
    float xv[16];
#pragma unroll
    for (int c = 0; c < Cn; c++) xv[c] = __ldcs(xp + c * HWn);

    float g0 = (gv.x + 1.0f) * 0.5f;
    float g1 = (gv.y + 1.0f) * 0.5f;
    float gi = fminf(fmaxf(fmaf(g0, 512.0f, 1.0f), 0.0f), 513.0f);
    float gj = fminf(fmaxf(fmaf(g1, 512.0f, 1.0f), 0.0f), 513.0f);

    int ii0 = (int)gi;
    int jj0 = (int)gj;
    float fi = gi - (float)ii0;
    float fj = gj - (float)jj0;
    float wi0 = 1.0f - fi, wi1 = fi;
    float wj0 = 1.0f - fj, wj1 = fj;

    int oi0 = ii0 - 1, oi1 = ii0;
    int oj0 = jj0 - 1, oj1 = jj0;
    bool vi0 = (unsigned)oi0 < (unsigned)Hn;
    bool vi1 = (unsigned)oi1 < (unsigned)Hn;
    bool vj0 = (unsigned)oj0 < (unsigned)Wn;
    bool vj1 = (unsigned)oj1 < (unsigned)Wn;

    bool  v00 = vi0 && vj0,       v01 = vi0 && vj1;
    bool  v10 = vi1 && vj0,       v11 = vi1 && vj1;
    int   o00 = oi0 * Wn + oj0,   o01 = oi0 * Wn + oj1;
    int   o10 = oi1 * Wn + oj0,   o11 = oi1 * Wn + oj1;
    float w00 = wi0 * wj0,        w01 = wi0 * wj1;
    float w10 = wi1 * wj0,        w11 = wi1 * wj1;

    // ---- D accumulation into 2x2-blocked layout ----
    // Parity of the anchor decides how many block-quads the patch spans.
    float* Db = g_D + b * HWn;
    int pi = oi0 & 1, pj = oj0 & 1;
    int ib0 = oi0 >> 1,       jb0 = oj0 >> 1;        // -1 only when invalid
    int ib1 = (oi0 + 1) >> 1, jb1 = (oj0 + 1) >> 1;
    if (pi == 0) {
        if (pj == 0) {
            // whole 2x2 patch in one quad (validity: even anchors imply
            // both rows/cols valid together)
            if (vi0 && vj0)
                red4(Db + (ib0 * 256 + jb0) * 4, w00, w01, w10, w11);
        } else {
            if (vi0 && vj0) red4(Db + (ib0 * 256 + jb0) * 4, 0.f, w00, 0.f, w10);
            if (vi0 && vj1) red4(Db + (ib0 * 256 + jb1) * 4, w01, 0.f, w11, 0.f);
        }
    } else {
        if (pj == 0) {
            if (vj0 && vi0) red4(Db + (ib0 * 256 + jb0) * 4, 0.f, 0.f, w00, w01);
            if (vj0 && vi1) red4(Db + (ib1 * 256 + jb0) * 4, w10, w11, 0.f, 0.f);
        } else {
            if (v00) atomicAdd(Db + (ib0 * 256 + jb0) * 4 + 3, w00);
            if (v01) atomicAdd(Db + (ib0 * 256 + jb1) * 4 + 2, w01);
            if (v10) atomicAdd(Db + (ib1 * 256 + jb0) * 4 + 1, w10);
            if (v11) atomicAdd(Db + (ib1 * 256 + jb1) * 4 + 0, w11);
        }
    }

    // Convert x to f16x2 once, then 2 x 16B A-RED per corner.
    uint32_t xh[8];
#pragma unroll
    for (int k = 0; k < 8; k++) {
        __half2 h = __floats2half2_rn(xv[2 * k], xv[2 * k + 1]);
        xh[k] = *reinterpret_cast<uint32_t*>(&h);
    }

    __half2* Ab = g_Ah + (size_t)b * HWn * 8;   // 8 half2 per pixel record
    emit_corner_h(v00, Ab + (size_t)o00 * 8, w00, xh);
    emit_corner_h(v01, Ab + (size_t)o01 * 8, w01, xh);
    emit_corner_h(v10, Ab + (size_t)o10 * 8, w10, xh);
    emit_corner_h(v11, Ab + (size_t)o11 * 8, w11, xh);
}

// ---------------------------------------------------------------------------
// Kernel 3: normalize + transpose [pix][c](f16) -> [c][pix](f32).
// One thread per (pixel-quad, channel-group); leader lane gathers D from the
// two blocked quads covering the 4 pixels, shfl-broadcast. rcp.approx.
// ---------------------------------------------------------------------------
__device__ __forceinline__ float frcp(float a) {
    float r;
    asm("rcp.approx.ftz.f32 %0, %1;" : "=f"(r) : "f"(a));
    return r;
}

__global__ void normalize_kernel(float4* __restrict__ out4) {
    int t = blockIdx.x * blockDim.x + threadIdx.x;
    if (t >= NPIX) return;
    int q = t >> 2;      // pixel quad id
    int g = t & 3;       // channel group (channels 4g..4g+3)
    int lane = threadIdx.x & 31;
    int lane0 = lane & ~3;

    int p0  = q * 4;
    int b   = p0 >> 18;
    int pix = p0 & (HWn - 1);

    float4 d;
    if (g == 0) {
        int i  = pix >> 9;          // row
        int jb = (pix & 511) >> 1;  // block-col of first pixel (even)
        const float4* D4 = reinterpret_cast<const float4*>(g_D);
        size_t blkbase = (size_t)b * (HWn / 4) + (i >> 1) * 256 + jb;
        float4 b0 = D4[blkbase];
        float4 b1 = D4[blkbase + 1];
        d = (i & 1) ? make_float4(b0.z, b0.w, b1.z, b1.w)
                    : make_float4(b0.x, b0.y, b1.x, b1.y);
    }
    d.x = __shfl_sync(0xFFFFFFFFu, d.x, lane0);
    d.y = __shfl_sync(0xFFFFFFFFu, d.y, lane0);
    d.z = __shfl_sync(0xFFFFFFFFu, d.z, lane0);
    d.w = __shfl_sync(0xFFFFFFFFu, d.w, lane0);

    float4 r, hf;
    bool bx = d.x > EPSF, by = d.y > EPSF, bz = d.z > EPSF, bw = d.w > EPSF;
    r.x = bx ? frcp(d.x + EPSF) : 0.0f;  hf.x = bx ? 0.0f : 1.0f;
    r.y = by ? frcp(d.y + EPSF) : 0.0f;  hf.y = by ? 0.0f : 1.0f;
    r.z = bz ? frcp(d.z + EPSF) : 0.0f;  hf.z = bz ? 0.0f : 1.0f;
    r.w = bw ? frcp(d.w + EPSF) : 0.0f;  hf.w = bw ? 0.0f : 1.0f;

    const uint2* A2 = reinterpret_cast<const uint2*>(g_Ah);
    uint2 u0 = A2[(size_t)(p0 + 0) * 4 + g];
    uint2 u1 = A2[(size_t)(p0 + 1) * 4 + g];
    uint2 u2 = A2[(size_t)(p0 + 2) * 4 + g];
    uint2 u3 = A2[(size_t)(p0 + 3) * 4 + g];

    float2 lo0 = __half22float2(*reinterpret_cast<const __half2*>(&u0.x));
    float2 hi0 = __half22float2(*reinterpret_cast<const __half2*>(&u0.y));
    float2 lo1 = __half22float2(*reinterpret_cast<const __half2*>(&u1.x));
    float2 hi1 = __half22float2(*reinterpret_cast<const __half2*>(&u1.y));
    float2 lo2 = __half22float2(*reinterpret_cast<const __half2*>(&u2.x));
    float2 hi2 = __half22float2(*reinterpret_cast<const __half2*>(&u2.y));
    float2 lo3 = __half22float2(*reinterpret_cast<const __half2*>(&u3.x));
    float2 hi3 = __half22float2(*reinterpret_cast<const __half2*>(&u3.y));

    float4 v0 = make_float4(fmaf(lo0.x, r.x, hf.x), fmaf(lo1.x, r.y, hf.y),
                            fmaf(lo2.x, r.z, hf.z), fmaf(lo3.x, r.w, hf.w));
    float4 v1 = make_float4(fmaf(lo0.y, r.x, hf.x), fmaf(lo1.y, r.y, hf.y),
                            fmaf(lo2.y, r.z, hf.z), fmaf(lo3.y, r.w, hf.w));
    float4 v2 = make_float4(fmaf(hi0.x, r.x, hf.x), fmaf(hi1.x, r.y, hf.y),
                            fmaf(hi2.x, r.z, hf.z), fmaf(hi3.x, r.w, hf.w));
    float4 v3 = make_float4(fmaf(hi0.y, r.x, hf.x), fmaf(hi1.y, r.y, hf.y),
                            fmaf(hi2.y, r.z, hf.z), fmaf(hi3.y, r.w, hf.w));

    float4* ob = out4 + ((size_t)b * Cn * HWn + pix) / 4;
    ob[(size_t)(4 * g + 0) * (HWn / 4)] = v0;
    ob[(size_t)(4 * g + 1) * (HWn / 4)] = v1;
    ob[(size_t)(4 * g + 2) * (HWn / 4)] = v2;
    ob[(size_t)(4 * g + 3) * (HWn / 4)] = v3;
}

// ---------------------------------------------------------------------------
extern "C" void kernel_launch(void* const* d_in, const int* in_sizes, int n_in,
                              void* d_out, int out_size) {
    const float* x    = (const float*)d_in[0];
    const float* grid = (const float*)d_in[1];
    float*       out  = (float*)d_out;

    {
        int total = (NOUT * 2) / 16 + NPIX / 4;
        zero_kernel<<<(total + 255) / 256, 256>>>();
    }
    scatter_kernel<<<NPIX / 256, 256>>>(x, grid);
    normalize_kernel<<<NPIX / 256, 256>>>((float4*)out);
}